// round 1
// baseline (speedup 1.0000x reference)
#include <cuda_runtime.h>
#include <cuda_bf16.h>
#include <math.h>

// Problem shapes (fixed for this instance)
#define BATCH 4
#define CH    512
#define HW    4096            // 64*64 tokens
#define GROUPS 32
#define CPG   (CH / GROUPS)   // 16
#define EPS   1e-6f

// ---------------- scratch (device globals; no allocation allowed) ----------
static __device__ float g_xn  [(size_t)BATCH * CH * HW];        // 32 MB
static __device__ float g_qkv [(size_t)BATCH * 3 * CH * HW];    // 100 MB
static __device__ float g_S   [(size_t)BATCH * HW * HW];        // 268 MB
static __device__ float g_ao  [(size_t)BATCH * CH * HW];        // 32 MB

// ---------------- GroupNorm ------------------------------------------------
__global__ __launch_bounds__(256) void groupnorm_kernel(
    const float* __restrict__ x, const float* __restrict__ gamma,
    const float* __restrict__ beta, float* __restrict__ xn)
{
    const int bg = blockIdx.x;          // b*GROUPS + g
    const int b  = bg >> 5;
    const int g  = bg & 31;
    const size_t base = ((size_t)b * CH + (size_t)g * CPG) * HW;
    const int n = CPG * HW;             // 65536

    float s = 0.f, ss = 0.f;
    for (int i = threadIdx.x; i < n; i += 256) {
        float v = x[base + i];
        s += v; ss += v * v;
    }
    // warp reduce
    #pragma unroll
    for (int o = 16; o > 0; o >>= 1) {
        s  += __shfl_xor_sync(0xffffffffu, s,  o);
        ss += __shfl_xor_sync(0xffffffffu, ss, o);
    }
    __shared__ float sh[18];
    const int w = threadIdx.x >> 5, l = threadIdx.x & 31;
    if (l == 0) { sh[w] = s; sh[8 + w] = ss; }
    __syncthreads();
    if (threadIdx.x == 0) {
        float S = 0.f, SS = 0.f;
        #pragma unroll
        for (int i = 0; i < 8; i++) { S += sh[i]; SS += sh[8 + i]; }
        float mean = S / (float)n;
        float var  = SS / (float)n - mean * mean;
        sh[16] = mean;
        sh[17] = rsqrtf(var + EPS);
    }
    __syncthreads();
    const float mean = sh[16], rstd = sh[17];

    for (int i = threadIdx.x; i < n; i += 256) {
        int c = g * CPG + (i >> 12);          // i / HW
        float v = (x[base + i] - mean) * rstd;
        xn[base + i] = v * gamma[c] + beta[c];
    }
}

// ---------------- generic SGEMM (128x128x8 tile, 8x8 per thread) -----------
// TA==0: A[m][k] (lda = row stride); TA==1: A[k][m]
// TB==0: B[k][n];                    TB==1: B[n][k]
template<int TA, int TB, bool BIAS, bool RESID>
__global__ __launch_bounds__(256) void sgemm_kernel(
    const float* __restrict__ A, const float* __restrict__ B,
    const float* __restrict__ bias, const float* __restrict__ resid,
    float* __restrict__ C,
    int M, int N, int K, int lda, int ldb, int ldc,
    float alpha, long long sA, long long sB, long long sC)
{
    const int bz = blockIdx.z;
    A += (long long)bz * sA;
    B += (long long)bz * sB;
    C += (long long)bz * sC;
    const float* R = RESID ? (resid + (long long)bz * sC) : nullptr;

    __shared__ float As[8][128];
    __shared__ float Bs[8][128];

    const int tid = threadIdx.x;
    const int m0 = blockIdx.y * 128;
    const int n0 = blockIdx.x * 128;
    const int row0 = (tid >> 4) * 8;   // 16 rows of threads
    const int col0 = (tid & 15) * 8;   // 16 cols of threads

    float acc[8][8];
    #pragma unroll
    for (int i = 0; i < 8; i++)
        #pragma unroll
        for (int j = 0; j < 8; j++) acc[i][j] = 0.f;

    for (int k0 = 0; k0 < K; k0 += 8) {
        #pragma unroll
        for (int it = 0; it < 4; it++) {
            int idx = tid + it * 256;
            if (TA == 0) {
                int m = idx >> 3, k = idx & 7;
                As[k][m] = A[(size_t)(m0 + m) * lda + (k0 + k)];
            } else {
                int k = idx >> 7, m = idx & 127;
                As[k][m] = A[(size_t)(k0 + k) * lda + (m0 + m)];
            }
        }
        #pragma unroll
        for (int it = 0; it < 4; it++) {
            int idx = tid + it * 256;
            if (TB == 0) {
                int k = idx >> 7, n = idx & 127;
                Bs[k][n] = B[(size_t)(k0 + k) * ldb + (n0 + n)];
            } else {
                int n = idx >> 3, k = idx & 7;
                Bs[k][n] = B[(size_t)(n0 + n) * ldb + (k0 + k)];
            }
        }
        __syncthreads();

        #pragma unroll
        for (int kk = 0; kk < 8; kk++) {
            float a[8], b[8];
            *(float4*)&a[0] = *(const float4*)&As[kk][row0];
            *(float4*)&a[4] = *(const float4*)&As[kk][row0 + 4];
            *(float4*)&b[0] = *(const float4*)&Bs[kk][col0];
            *(float4*)&b[4] = *(const float4*)&Bs[kk][col0 + 4];
            #pragma unroll
            for (int i = 0; i < 8; i++)
                #pragma unroll
                for (int j = 0; j < 8; j++)
                    acc[i][j] = fmaf(a[i], b[j], acc[i][j]);
        }
        __syncthreads();
    }

    // epilogue
    #pragma unroll
    for (int i = 0; i < 8; i++) {
        const int m = m0 + row0 + i;
        const float bv = BIAS ? bias[m] : 0.f;
        const size_t off = (size_t)m * ldc + (n0 + col0);
        #pragma unroll
        for (int jj = 0; jj < 2; jj++) {
            float4 r;
            float4 rr;
            if (RESID) rr = *(const float4*)&R[off + jj * 4];
            r.x = alpha * acc[i][jj * 4 + 0] + bv;
            r.y = alpha * acc[i][jj * 4 + 1] + bv;
            r.z = alpha * acc[i][jj * 4 + 2] + bv;
            r.w = alpha * acc[i][jj * 4 + 3] + bv;
            if (RESID) { r.x += rr.x; r.y += rr.y; r.z += rr.z; r.w += rr.w; }
            *(float4*)&C[off + jj * 4] = r;
        }
    }
}

// ---------------- row softmax over 4096-wide rows ---------------------------
__global__ __launch_bounds__(256) void softmax_kernel(float* __restrict__ S)
{
    const size_t row = blockIdx.x;
    float* p = S + row * (size_t)HW;

    float v[16];
    float mx = -INFINITY;
    #pragma unroll
    for (int i = 0; i < 16; i++) {
        v[i] = p[threadIdx.x + i * 256];
        mx = fmaxf(mx, v[i]);
    }
    #pragma unroll
    for (int o = 16; o > 0; o >>= 1)
        mx = fmaxf(mx, __shfl_xor_sync(0xffffffffu, mx, o));

    __shared__ float sh[10];
    const int w = threadIdx.x >> 5, l = threadIdx.x & 31;
    if (l == 0) sh[w] = mx;
    __syncthreads();
    if (threadIdx.x == 0) {
        float m = sh[0];
        #pragma unroll
        for (int i = 1; i < 8; i++) m = fmaxf(m, sh[i]);
        sh[8] = m;
    }
    __syncthreads();
    mx = sh[8];

    float sum = 0.f;
    #pragma unroll
    for (int i = 0; i < 16; i++) {
        v[i] = __expf(v[i] - mx);
        sum += v[i];
    }
    #pragma unroll
    for (int o = 16; o > 0; o >>= 1)
        sum += __shfl_xor_sync(0xffffffffu, sum, o);
    if (l == 0) sh[w] = sum;
    __syncthreads();
    if (threadIdx.x == 0) {
        float s = 0.f;
        #pragma unroll
        for (int i = 0; i < 8; i++) s += sh[i];
        sh[9] = 1.f / s;
    }
    __syncthreads();
    const float inv = sh[9];

    #pragma unroll
    for (int i = 0; i < 16; i++)
        p[threadIdx.x + i * 256] = v[i] * inv;
}

// ---------------- launch -----------------------------------------------------
extern "C" void kernel_launch(void* const* d_in, const int* in_sizes, int n_in,
                              void* d_out, int out_size)
{
    const float* x      = (const float*)d_in[0];
    const float* gamma  = (const float*)d_in[1];
    const float* beta   = (const float*)d_in[2];
    const float* w_qkv  = (const float*)d_in[3];
    const float* b_qkv  = (const float*)d_in[4];
    const float* w_proj = (const float*)d_in[5];
    const float* b_proj = (const float*)d_in[6];
    float* out = (float*)d_out;

    float *xn, *qkv, *S, *ao;
    cudaGetSymbolAddress((void**)&xn,  g_xn);
    cudaGetSymbolAddress((void**)&qkv, g_qkv);
    cudaGetSymbolAddress((void**)&S,   g_S);
    cudaGetSymbolAddress((void**)&ao,  g_ao);

    const long long sXN  = (long long)CH * HW;          // 512*4096
    const long long sQKV = (long long)3 * CH * HW;      // 1536*4096
    const long long sS   = (long long)HW * HW;          // 4096*4096
    const float scale2 = 1.f / sqrtf((float)CH);        // (c^-0.25)^2

    // 1) GroupNorm
    groupnorm_kernel<<<BATCH * GROUPS, 256>>>(x, gamma, beta, xn);

    // 2) QKV = W_qkv @ xn + b_qkv     (M=1536, N=4096, K=512)
    {
        dim3 g(HW / 128, (3 * CH) / 128, BATCH);
        sgemm_kernel<0, 0, true, false><<<g, 256>>>(
            w_qkv, xn, b_qkv, nullptr, qkv,
            3 * CH, HW, CH, CH, HW, HW,
            1.f, 0, sXN, sQKV);
    }

    // 3) S = (Q^T K) * scale^2        (M=N=4096, K=512)  A=q (c x N, trans), B=k
    {
        dim3 g(HW / 128, HW / 128, BATCH);
        sgemm_kernel<1, 0, false, false><<<g, 256>>>(
            qkv,                 /* q at offset 0   */
            qkv + (size_t)CH * HW, /* k */
            nullptr, nullptr, S,
            HW, HW, CH, HW, HW, HW,
            scale2, sQKV, sQKV, sS);
    }

    // 4) softmax over rows of S
    softmax_kernel<<<BATCH * HW, 256>>>(S);

    // 5) O = V @ P^T                  (M=512, N=4096, K=4096)  B=P (n x k)
    {
        dim3 g(HW / 128, CH / 128, BATCH);
        sgemm_kernel<0, 1, false, false><<<g, 256>>>(
            qkv + (size_t)2 * CH * HW, /* v */
            S, nullptr, nullptr, ao,
            CH, HW, HW, HW, HW, HW,
            1.f, sQKV, sS, sXN);
    }

    // 6) out = W_proj @ O + b_proj + x    (M=512, N=4096, K=512)
    {
        dim3 g(HW / 128, CH / 128, BATCH);
        sgemm_kernel<0, 0, true, true><<<g, 256>>>(
            w_proj, ao, b_proj, x, out,
            CH, HW, CH, CH, HW, HW,
            1.f, 0, sXN, sXN);
    }
}

// round 5
// speedup vs baseline: 3.4675x; 3.4675x over previous
#include <cuda_runtime.h>
#include <cuda_bf16.h>
#include <math.h>
#include <stdint.h>

#define BATCH 4
#define CH    512
#define HW    4096
#define EPS   1e-6f

// ---------------- device scratch (statics; no runtime alloc) ----------------
static __device__ float g_mean[BATCH * 32];
static __device__ float g_rstd[BATCH * 32];
static __device__ __align__(256) __nv_bfloat16 g_xnT_h[(size_t)BATCH * HW * CH];
static __device__ __align__(256) __nv_bfloat16 g_xnT_l[(size_t)BATCH * HW * CH];
static __device__ __align__(256) __nv_bfloat16 g_wqkv_h[3 * CH * CH];
static __device__ __align__(256) __nv_bfloat16 g_wqkv_l[3 * CH * CH];
static __device__ __align__(256) __nv_bfloat16 g_wproj_h[CH * CH];
static __device__ __align__(256) __nv_bfloat16 g_wproj_l[CH * CH];
static __device__ __align__(256) __nv_bfloat16 g_qk_h[(size_t)BATCH * HW * 1024];   // q|k [tok][1024]
static __device__ __align__(256) __nv_bfloat16 g_qk_l[(size_t)BATCH * HW * 1024];
static __device__ __align__(256) __nv_bfloat16 g_v_h[(size_t)BATCH * CH * HW];      // v [c][tok]
static __device__ __align__(256) __nv_bfloat16 g_v_l[(size_t)BATCH * CH * HW];
static __device__ __align__(256) float         g_S  [(size_t)BATCH * HW * HW];      // fp32 logits
static __device__ __align__(256) __nv_bfloat16 g_p_h[(size_t)BATCH * HW * HW];      // softmax [i][j]
static __device__ __align__(256) __nv_bfloat16 g_p_l[(size_t)BATCH * HW * HW];
static __device__ __align__(256) __nv_bfloat16 g_oT_h[(size_t)BATCH * HW * CH];     // O^T [tok][c]
static __device__ __align__(256) __nv_bfloat16 g_oT_l[(size_t)BATCH * HW * CH];

// ---------------- helpers ----------------
__device__ __forceinline__ uint32_t smem_u32(const void* p) {
    uint32_t a;
    asm("{ .reg .u64 t; cvta.to.shared.u64 t, %1; cvt.u32.u64 %0, t; }" : "=r"(a) : "l"(p));
    return a;
}

__device__ __forceinline__ void cp16(uint32_t dst, const void* src) {
    asm volatile("cp.async.cg.shared.global [%0], [%1], 16;" :: "r"(dst), "l"(src));
}
#define CP_COMMIT() asm volatile("cp.async.commit_group;" ::: "memory")
#define CP_WAIT1()  asm volatile("cp.async.wait_group 1;" ::: "memory")
#define CP_WAIT0()  asm volatile("cp.async.wait_group 0;" ::: "memory")

__device__ __forceinline__ void ldm4(uint32_t* r, uint32_t addr) {
    asm volatile("ldmatrix.sync.aligned.m8n8.x4.shared.b16 {%0,%1,%2,%3}, [%4];"
                 : "=r"(r[0]), "=r"(r[1]), "=r"(r[2]), "=r"(r[3]) : "r"(addr));
}

__device__ __forceinline__ void mma16816(float* d, const uint32_t* a, const uint32_t* b) {
    asm volatile(
        "mma.sync.aligned.m16n8k16.row.col.f32.bf16.bf16.f32 "
        "{%0,%1,%2,%3}, {%4,%5,%6,%7}, {%8,%9}, {%0,%1,%2,%3};"
        : "+f"(d[0]), "+f"(d[1]), "+f"(d[2]), "+f"(d[3])
        : "r"(a[0]), "r"(a[1]), "r"(a[2]), "r"(a[3]), "r"(b[0]), "r"(b[1]));
}

__device__ __forceinline__ uint32_t bpack(float a, float b) {
    __nv_bfloat162 t = __floats2bfloat162_rn(a, b);
    return *reinterpret_cast<uint32_t*>(&t);
}
__device__ __forceinline__ float bres(float v) {
    return v - __bfloat162float(__float2bfloat16(v));
}

#define SMEM_BYTES 131072   // 2 stages x 4 tiles x 16KB

// ---------------- split-bf16 GEMM: C = A * B^T (3-pass hi/lo) ----------------
// A: [M][K] hi/lo (lda); B: [N][K] hi/lo (ldb). Tiles 128x128, K mult of 64.
// EPI: 0=QKV  1=S(fp32*alpha)  2=O(bf16 split row-major)  3=PROJ(transposed+bias+resid)
template<int EPI>
__global__ __launch_bounds__(256, 1) void mma_gemm_kernel(
    const __nv_bfloat16* __restrict__ Ah, const __nv_bfloat16* __restrict__ Al,
    int lda, long long sA,
    const __nv_bfloat16* __restrict__ Bh, const __nv_bfloat16* __restrict__ Bl,
    int ldb, long long sB,
    int K, float alpha, const float* __restrict__ bias,
    float* __restrict__ Cf, long long sCf,
    __nv_bfloat16* __restrict__ Ch, __nv_bfloat16* __restrict__ Cl, long long sC,
    __nv_bfloat16* __restrict__ Vh, __nv_bfloat16* __restrict__ Vl, long long sV,
    const float* __restrict__ Res, long long sRes)
{
    extern __shared__ char smem[];
    const uint32_t sb = smem_u32(smem);
    const int tid = threadIdx.x, lid = tid & 31, wid = tid >> 5;
    const int bz = blockIdx.z;
    const int m0 = blockIdx.y * 128, n0 = blockIdx.x * 128;

    Ah += (long long)bz * sA;  Al += (long long)bz * sA;
    Bh += (long long)bz * sB;  Bl += (long long)bz * sB;

    const int wm0 = (wid >> 2) * 64, wn0 = (wid & 3) * 32;

    // ---- loader (thread covers seg=tid&7, rows tid>>3 + i*32) ----
    const int l_r0 = tid >> 3, l_seg = tid & 7;
    auto load_stage = [&](int s, int kIter) {
        const uint32_t dst = sb + s * 65536;
        const int k0 = kIter << 6;
        #pragma unroll
        for (int i = 0; i < 4; i++) {
            const int row = l_r0 + i * 32;
            const uint32_t so = row * 128 + ((l_seg ^ (row & 7)) << 4);
            const size_t ga = (size_t)(m0 + row) * lda + k0 + l_seg * 8;
            const size_t gb = (size_t)(n0 + row) * ldb + k0 + l_seg * 8;
            cp16(dst + so,         Ah + ga);
            cp16(dst + 16384 + so, Al + ga);
            cp16(dst + 32768 + so, Bh + gb);
            cp16(dst + 49152 + so, Bl + gb);
        }
    };

    // ---- fragment lane constants ----
    const int matq = lid >> 3, mr = lid & 7;
    const int a_rb = ((matq & 1) << 3) + mr;   // row-in-16 for A
    const int a_ks = matq >> 1;                // k-16B-seg select for A
    const int b_rb = (((matq >> 1) & 1) << 3) + mr;
    const int b_ks = matq & 1;

    float acc[4][4][4];
    #pragma unroll
    for (int i = 0; i < 4; i++)
        #pragma unroll
        for (int j = 0; j < 4; j++)
            #pragma unroll
            for (int q = 0; q < 4; q++) acc[i][j][q] = 0.f;

    const int niter = K >> 6;
    load_stage(0, 0); CP_COMMIT();
    load_stage(1, 1); CP_COMMIT();
    CP_WAIT1();
    __syncthreads();

    for (int it = 0; it < niter; it++) {
        const uint32_t Ab = sb + (it & 1) * 65536;
        #pragma unroll
        for (int ks = 0; ks < 4; ks++) {
            uint32_t ah[4][4], al[4][4], bh[2][4], bl[2][4];
            #pragma unroll
            for (int mt = 0; mt < 4; mt++) {
                const int r = wm0 + mt * 16 + a_rb;
                const uint32_t ad = Ab + r * 128 + (((ks * 2 + a_ks) ^ (r & 7)) << 4);
                ldm4(ah[mt], ad);
                ldm4(al[mt], ad + 16384);
            }
            #pragma unroll
            for (int g = 0; g < 2; g++) {
                const int r = wn0 + g * 16 + b_rb;
                const uint32_t bd = Ab + 32768 + r * 128 + (((ks * 2 + b_ks) ^ (r & 7)) << 4);
                ldm4(bh[g], bd);
                ldm4(bl[g], bd + 16384);
            }
            #pragma unroll
            for (int mt = 0; mt < 4; mt++)
                #pragma unroll
                for (int nt = 0; nt < 4; nt++) {
                    const uint32_t* bhp = &bh[nt >> 1][(nt & 1) * 2];
                    const uint32_t* blp = &bl[nt >> 1][(nt & 1) * 2];
                    mma16816(acc[mt][nt], ah[mt], bhp);
                    mma16816(acc[mt][nt], ah[mt], blp);
                    mma16816(acc[mt][nt], al[mt], bhp);
                }
        }
        __syncthreads();
        if (it + 2 < niter) {
            load_stage(it & 1, it + 2); CP_COMMIT(); CP_WAIT1();
        } else {
            CP_COMMIT(); CP_WAIT0();
        }
        __syncthreads();
    }

    // ---- stage fp32 tile to smem (stride 133: conflict-free transpose) ----
    float* cs = reinterpret_cast<float*>(smem);
    #pragma unroll
    for (int mt = 0; mt < 4; mt++) {
        const int r = wm0 + mt * 16 + (lid >> 2);
        #pragma unroll
        for (int nt = 0; nt < 4; nt++) {
            const int c = wn0 + nt * 8 + ((lid & 3) << 1);
            cs[r * 133 + c]           = acc[mt][nt][0];
            cs[r * 133 + c + 1]       = acc[mt][nt][1];
            cs[(r + 8) * 133 + c]     = acc[mt][nt][2];
            cs[(r + 8) * 133 + c + 1] = acc[mt][nt][3];
        }
    }
    __syncthreads();

    // ---- epilogue ----
    if (EPI == 0) {
        if (n0 < 1024) {   // q/k rows: [tok][1024] split bf16, +bias
            const float4 bv = *reinterpret_cast<const float4*>(&bias[n0 + lid * 4]);
            __nv_bfloat16* H = Ch + (size_t)bz * sC;
            __nv_bfloat16* L = Cl + (size_t)bz * sC;
            for (int r = wid; r < 128; r += 8) {
                const float* row = cs + r * 133 + lid * 4;
                const float v0 = row[0] + bv.x, v1 = row[1] + bv.y;
                const float v2 = row[2] + bv.z, v3 = row[3] + bv.w;
                const size_t o = (size_t)(m0 + r) * 1024 + n0 + lid * 4;
                uint2 hi; hi.x = bpack(v0, v1); hi.y = bpack(v2, v3);
                uint2 lo; lo.x = bpack(bres(v0), bres(v1)); lo.y = bpack(bres(v2), bres(v3));
                *reinterpret_cast<uint2*>(H + o) = hi;
                *reinterpret_cast<uint2*>(L + o) = lo;
            }
        } else {           // v: [c][tok] split bf16, +bias
            __nv_bfloat16* H = Vh + (size_t)bz * sV;
            __nv_bfloat16* L = Vl + (size_t)bz * sV;
            for (int c = wid; c < 128; c += 8) {
                const int n = n0 + c;
                const float bvn = bias[n];
                const float v0 = cs[(lid * 4 + 0) * 133 + c] + bvn;
                const float v1 = cs[(lid * 4 + 1) * 133 + c] + bvn;
                const float v2 = cs[(lid * 4 + 2) * 133 + c] + bvn;
                const float v3 = cs[(lid * 4 + 3) * 133 + c] + bvn;
                const size_t o = (size_t)(n - 1024) * HW + m0 + lid * 4;
                uint2 hi; hi.x = bpack(v0, v1); hi.y = bpack(v2, v3);
                uint2 lo; lo.x = bpack(bres(v0), bres(v1)); lo.y = bpack(bres(v2), bres(v3));
                *reinterpret_cast<uint2*>(H + o) = hi;
                *reinterpret_cast<uint2*>(L + o) = lo;
            }
        }
    } else if (EPI == 1) {  // S: fp32 row-major * alpha
        float* C = Cf + (size_t)bz * sCf;
        for (int r = wid; r < 128; r += 8) {
            const float* row = cs + r * 133 + lid * 4;
            float4 v;
            v.x = row[0] * alpha; v.y = row[1] * alpha;
            v.z = row[2] * alpha; v.w = row[3] * alpha;
            *reinterpret_cast<float4*>(C + (size_t)(m0 + r) * HW + n0 + lid * 4) = v;
        }
    } else if (EPI == 2) {  // O^T: [tok][c] split bf16
        __nv_bfloat16* H = Ch + (size_t)bz * sC;
        __nv_bfloat16* L = Cl + (size_t)bz * sC;
        for (int r = wid; r < 128; r += 8) {
            const float* row = cs + r * 133 + lid * 4;
            const float v0 = row[0], v1 = row[1], v2 = row[2], v3 = row[3];
            const size_t o = (size_t)(m0 + r) * CH + n0 + lid * 4;
            uint2 hi; hi.x = bpack(v0, v1); hi.y = bpack(v2, v3);
            uint2 lo; lo.x = bpack(bres(v0), bres(v1)); lo.y = bpack(bres(v2), bres(v3));
            *reinterpret_cast<uint2*>(H + o) = hi;
            *reinterpret_cast<uint2*>(L + o) = lo;
        }
    } else {                // PROJ: out[c][tok] = tile^T + bias + residual (fp32)
        const float* R = Res + (size_t)bz * sRes;
        float* C = Cf + (size_t)bz * sCf;
        for (int c = wid; c < 128; c += 8) {
            const int n = n0 + c;
            const float bvn = bias[n];
            const size_t o = (size_t)n * HW + m0 + lid * 4;
            const float4 rr = *reinterpret_cast<const float4*>(R + o);
            float4 v;
            v.x = cs[(lid * 4 + 0) * 133 + c] + bvn + rr.x;
            v.y = cs[(lid * 4 + 1) * 133 + c] + bvn + rr.y;
            v.z = cs[(lid * 4 + 2) * 133 + c] + bvn + rr.z;
            v.w = cs[(lid * 4 + 3) * 133 + c] + bvn + rr.w;
            *reinterpret_cast<float4*>(C + o) = v;
        }
    }
}

// ---------------- GroupNorm stats ----------------
__global__ __launch_bounds__(256) void gn_stats_kernel(const float* __restrict__ x)
{
    const int bg = blockIdx.x;
    const size_t base = (size_t)bg * 16 * HW;
    const int n = 16 * HW;
    float s = 0.f, ss = 0.f;
    for (int i = threadIdx.x; i < n; i += 256) {
        float v = x[base + i];
        s += v; ss += v * v;
    }
    #pragma unroll
    for (int o = 16; o > 0; o >>= 1) {
        s  += __shfl_xor_sync(0xffffffffu, s,  o);
        ss += __shfl_xor_sync(0xffffffffu, ss, o);
    }
    __shared__ float sh[16];
    const int w = threadIdx.x >> 5, l = threadIdx.x & 31;
    if (l == 0) { sh[w] = s; sh[8 + w] = ss; }
    __syncthreads();
    if (threadIdx.x == 0) {
        float S = 0.f, SS = 0.f;
        #pragma unroll
        for (int i = 0; i < 8; i++) { S += sh[i]; SS += sh[8 + i]; }
        float mean = S / (float)n;
        float var  = SS / (float)n - mean * mean;
        g_mean[bg] = mean;
        g_rstd[bg] = rsqrtf(var + EPS);
    }
}

// ---------------- normalize + transpose + bf16 split ----------------
__global__ __launch_bounds__(256) void normT_kernel(
    const float* __restrict__ x, const float* __restrict__ gamma,
    const float* __restrict__ beta,
    __nv_bfloat16* __restrict__ th, __nv_bfloat16* __restrict__ tl)
{
    __shared__ float tile[64][65];
    const int b = blockIdx.z, c0 = blockIdx.y * 64, t0 = blockIdx.x * 64;
    const int lane = threadIdx.x & 63, r0 = threadIdx.x >> 6;
    #pragma unroll
    for (int r = r0; r < 64; r += 4) {
        const int c = c0 + r;
        const int gr = b * 32 + (c >> 4);
        float v = x[((size_t)b * CH + c) * HW + t0 + lane];
        tile[r][lane] = (v - g_mean[gr]) * g_rstd[gr] * gamma[c] + beta[c];
    }
    __syncthreads();
    #pragma unroll
    for (int r = r0; r < 64; r += 4) {
        const float v = tile[lane][r];
        const size_t o = ((size_t)b * HW + t0 + r) * CH + c0 + lane;
        __nv_bfloat16 hv = __float2bfloat16(v);
        th[o] = hv;
        tl[o] = __float2bfloat16(v - __bfloat162float(hv));
    }
}

// ---------------- weight fp32 -> hi/lo split ----------------
__global__ void wsplit_kernel(const float* __restrict__ in,
                              __nv_bfloat16* __restrict__ h,
                              __nv_bfloat16* __restrict__ l, int n)
{
    int i = blockIdx.x * 256 + threadIdx.x;
    if (i < n) {
        float v = in[i];
        __nv_bfloat16 hv = __float2bfloat16(v);
        h[i] = hv;
        l[i] = __float2bfloat16(v - __bfloat162float(hv));
    }
}

// ---------------- softmax (fp32 in, bf16 split out) ----------------
__global__ __launch_bounds__(256) void softmax_kernel(
    const float* __restrict__ S, __nv_bfloat16* __restrict__ ph,
    __nv_bfloat16* __restrict__ pl)
{
    const size_t base = (size_t)blockIdx.x * HW;
    const float* p = S + base;

    float v[16];
    float mx = -INFINITY;
    #pragma unroll
    for (int i = 0; i < 16; i++) {
        v[i] = p[threadIdx.x + i * 256];
        mx = fmaxf(mx, v[i]);
    }
    #pragma unroll
    for (int o = 16; o > 0; o >>= 1)
        mx = fmaxf(mx, __shfl_xor_sync(0xffffffffu, mx, o));

    __shared__ float sh[10];
    const int w = threadIdx.x >> 5, l = threadIdx.x & 31;
    if (l == 0) sh[w] = mx;
    __syncthreads();
    if (threadIdx.x == 0) {
        float m = sh[0];
        #pragma unroll
        for (int i = 1; i < 8; i++) m = fmaxf(m, sh[i]);
        sh[8] = m;
    }
    __syncthreads();
    mx = sh[8];

    float sum = 0.f;
    #pragma unroll
    for (int i = 0; i < 16; i++) { v[i] = __expf(v[i] - mx); sum += v[i]; }
    #pragma unroll
    for (int o = 16; o > 0; o >>= 1)
        sum += __shfl_xor_sync(0xffffffffu, sum, o);
    if (l == 0) sh[w] = sum;
    __syncthreads();
    if (threadIdx.x == 0) {
        float s = 0.f;
        #pragma unroll
        for (int i = 0; i < 8; i++) s += sh[i];
        sh[9] = 1.f / s;
    }
    __syncthreads();
    const float inv = sh[9];

    #pragma unroll
    for (int i = 0; i < 16; i++) {
        const float pv = v[i] * inv;
        const size_t o = base + threadIdx.x + i * 256;
        __nv_bfloat16 hv = __float2bfloat16(pv);
        ph[o] = hv;
        pl[o] = __float2bfloat16(pv - __bfloat162float(hv));
    }
}

// ---------------- launch ----------------
extern "C" void kernel_launch(void* const* d_in, const int* in_sizes, int n_in,
                              void* d_out, int out_size)
{
    const float* x      = (const float*)d_in[0];
    const float* gamma  = (const float*)d_in[1];
    const float* beta   = (const float*)d_in[2];
    const float* w_qkv  = (const float*)d_in[3];
    const float* b_qkv  = (const float*)d_in[4];
    const float* w_proj = (const float*)d_in[5];
    const float* b_proj = (const float*)d_in[6];
    float* out = (float*)d_out;

    __nv_bfloat16 *xnT_h, *xnT_l, *wqkv_h, *wqkv_l, *wproj_h, *wproj_l;
    __nv_bfloat16 *qk_h, *qk_l, *v_h, *v_l, *p_h, *p_l, *oT_h, *oT_l;
    float* S;
    cudaGetSymbolAddress((void**)&xnT_h, g_xnT_h);
    cudaGetSymbolAddress((void**)&xnT_l, g_xnT_l);
    cudaGetSymbolAddress((void**)&wqkv_h, g_wqkv_h);
    cudaGetSymbolAddress((void**)&wqkv_l, g_wqkv_l);
    cudaGetSymbolAddress((void**)&wproj_h, g_wproj_h);
    cudaGetSymbolAddress((void**)&wproj_l, g_wproj_l);
    cudaGetSymbolAddress((void**)&qk_h, g_qk_h);
    cudaGetSymbolAddress((void**)&qk_l, g_qk_l);
    cudaGetSymbolAddress((void**)&v_h, g_v_h);
    cudaGetSymbolAddress((void**)&v_l, g_v_l);
    cudaGetSymbolAddress((void**)&S, g_S);
    cudaGetSymbolAddress((void**)&p_h, g_p_h);
    cudaGetSymbolAddress((void**)&p_l, g_p_l);
    cudaGetSymbolAddress((void**)&oT_h, g_oT_h);
    cudaGetSymbolAddress((void**)&oT_l, g_oT_l);

    cudaFuncSetAttribute(mma_gemm_kernel<0>, cudaFuncAttributeMaxDynamicSharedMemorySize, SMEM_BYTES);
    cudaFuncSetAttribute(mma_gemm_kernel<1>, cudaFuncAttributeMaxDynamicSharedMemorySize, SMEM_BYTES);
    cudaFuncSetAttribute(mma_gemm_kernel<2>, cudaFuncAttributeMaxDynamicSharedMemorySize, SMEM_BYTES);
    cudaFuncSetAttribute(mma_gemm_kernel<3>, cudaFuncAttributeMaxDynamicSharedMemorySize, SMEM_BYTES);

    const long long sTok = (long long)HW * CH;
    const long long sQK  = (long long)HW * 1024;
    const long long sS   = (long long)HW * HW;
    const float scale2 = 1.f / sqrtf((float)CH);

    // 1) weight splits
    wsplit_kernel<<<(3 * CH * CH + 255) / 256, 256>>>(w_qkv, wqkv_h, wqkv_l, 3 * CH * CH);
    wsplit_kernel<<<(CH * CH + 255) / 256, 256>>>(w_proj, wproj_h, wproj_l, CH * CH);

    // 2) GroupNorm stats + normalize/transpose/split
    gn_stats_kernel<<<BATCH * 32, 256>>>(x);
    normT_kernel<<<dim3(HW / 64, CH / 64, BATCH), 256>>>(x, gamma, beta, xnT_h, xnT_l);

    // 3) QKV: C[tok][oc] = xnT . w_qkv^T  (M=4096, N=1536, K=512)
    mma_gemm_kernel<0><<<dim3(12, 32, BATCH), 256, SMEM_BYTES>>>(
        xnT_h, xnT_l, CH, sTok, wqkv_h, wqkv_l, CH, 0,
        CH, 1.f, b_qkv,
        nullptr, 0, qk_h, qk_l, sQK, v_h, v_l, sTok, nullptr, 0);

    // 4) S[i][j] = q . k^T * scale  (M=N=4096, K=512)
    mma_gemm_kernel<1><<<dim3(32, 32, BATCH), 256, SMEM_BYTES>>>(
        qk_h, qk_l, 1024, sQK, qk_h + CH, qk_l + CH, 1024, sQK,
        CH, scale2, nullptr,
        S, sS, nullptr, nullptr, 0, nullptr, nullptr, 0, nullptr, 0);

    // 5) softmax rows -> p hi/lo
    softmax_kernel<<<BATCH * HW, 256>>>(S, p_h, p_l);

    // 6) O^T[tok][c] = p . v^T  (M=4096, N=512, K=4096)
    mma_gemm_kernel<2><<<dim3(4, 32, BATCH), 256, SMEM_BYTES>>>(
        p_h, p_l, HW, sS, v_h, v_l, HW, sTok,
        HW, 1.f, nullptr,
        nullptr, 0, oT_h, oT_l, sTok, nullptr, nullptr, 0, nullptr, 0);

    // 7) out[c][tok] = oT . w_proj^T + b_proj + x  (M=4096, N=512, K=512)
    mma_gemm_kernel<3><<<dim3(4, 32, BATCH), 256, SMEM_BYTES>>>(
        oT_h, oT_l, CH, sTok, wproj_h, wproj_l, CH, 0,
        CH, 1.f, b_proj,
        out, sTok, nullptr, nullptr, 0, nullptr, nullptr, 0, x, sTok);
}

// round 6
// speedup vs baseline: 4.2967x; 1.2392x over previous
#include <cuda_runtime.h>
#include <cuda_bf16.h>
#include <math.h>
#include <stdint.h>

#define BATCH 4
#define CH    512
#define HW    4096
#define EPS   1e-6f

// ---------------- device scratch (statics; no runtime alloc) ----------------
static __device__ float g_mean[BATCH * 32];
static __device__ float g_rstd[BATCH * 32];
static __device__ __align__(256) __nv_bfloat16 g_xnT_h[(size_t)BATCH * HW * CH];
static __device__ __align__(256) __nv_bfloat16 g_xnT_l[(size_t)BATCH * HW * CH];
static __device__ __align__(256) __nv_bfloat16 g_wqkv_h[3 * CH * CH];
static __device__ __align__(256) __nv_bfloat16 g_wqkv_l[3 * CH * CH];
static __device__ __align__(256) __nv_bfloat16 g_wproj_h[CH * CH];
static __device__ __align__(256) __nv_bfloat16 g_wproj_l[CH * CH];
static __device__ __align__(256) __nv_bfloat16 g_qk_h[(size_t)BATCH * HW * 1024];   // q|k [tok][1024]
static __device__ __align__(256) __nv_bfloat16 g_qk_l[(size_t)BATCH * HW * 1024];
static __device__ __align__(256) __nv_bfloat16 g_v_h[(size_t)BATCH * CH * HW];      // v [c][tok]
static __device__ __align__(256) float         g_S  [(size_t)BATCH * HW * HW];      // fp32 logits
static __device__ __align__(256) __nv_bfloat16 g_p_h[(size_t)BATCH * HW * HW];      // softmax [i][j]
static __device__ __align__(256) __nv_bfloat16 g_p_l[(size_t)BATCH * HW * HW];
static __device__ __align__(256) __nv_bfloat16 g_oT_h[(size_t)BATCH * HW * CH];     // O^T [tok][c]
static __device__ __align__(256) __nv_bfloat16 g_oT_l[(size_t)BATCH * HW * CH];

// ---------------- helpers ----------------
__device__ __forceinline__ uint32_t smem_u32(const void* p) {
    uint32_t a;
    asm("{ .reg .u64 t; cvta.to.shared.u64 t, %1; cvt.u32.u64 %0, t; }" : "=r"(a) : "l"(p));
    return a;
}

__device__ __forceinline__ void cp16(uint32_t dst, const void* src) {
    asm volatile("cp.async.cg.shared.global [%0], [%1], 16;" :: "r"(dst), "l"(src));
}
#define CP_COMMIT() asm volatile("cp.async.commit_group;" ::: "memory")
#define CP_WAIT1()  asm volatile("cp.async.wait_group 1;" ::: "memory")
#define CP_WAIT0()  asm volatile("cp.async.wait_group 0;" ::: "memory")

__device__ __forceinline__ void ldm4(uint32_t* r, uint32_t addr) {
    asm volatile("ldmatrix.sync.aligned.m8n8.x4.shared.b16 {%0,%1,%2,%3}, [%4];"
                 : "=r"(r[0]), "=r"(r[1]), "=r"(r[2]), "=r"(r[3]) : "r"(addr));
}

__device__ __forceinline__ void mma16816(float* d, const uint32_t* a, const uint32_t* b) {
    asm volatile(
        "mma.sync.aligned.m16n8k16.row.col.f32.bf16.bf16.f32 "
        "{%0,%1,%2,%3}, {%4,%5,%6,%7}, {%8,%9}, {%0,%1,%2,%3};"
        : "+f"(d[0]), "+f"(d[1]), "+f"(d[2]), "+f"(d[3])
        : "r"(a[0]), "r"(a[1]), "r"(a[2]), "r"(a[3]), "r"(b[0]), "r"(b[1]));
}

__device__ __forceinline__ uint32_t bpack(float a, float b) {
    __nv_bfloat162 t = __floats2bfloat162_rn(a, b);
    return *reinterpret_cast<uint32_t*>(&t);
}
__device__ __forceinline__ float bres(float v) {
    return v - __bfloat162float(__float2bfloat16(v));
}

#define SMEM_BYTES 131072   // 2 stages x 4 tiles x 16KB

// ---------------- split-bf16 GEMM: C = A * B^T ----------------
// A: [M][K] hi/lo (lda); B: [N][K] hi(/lo) (ldb). Tiles 128x128, K mult of 64.
// SB: true = 3-pass (B split), false = 2-pass ((ah+al)*bh, B single bf16)
// EPI: 0=QKV  1=S(fp32*alpha)  2=O(bf16 split row-major)  3=PROJ(transposed+bias+resid)
template<int EPI, bool SB>
__global__ __launch_bounds__(256, 1) void mma_gemm_kernel(
    const __nv_bfloat16* __restrict__ Ah, const __nv_bfloat16* __restrict__ Al,
    int lda, long long sA,
    const __nv_bfloat16* __restrict__ Bh, const __nv_bfloat16* __restrict__ Bl,
    int ldb, long long sB,
    int K, float alpha, const float* __restrict__ bias,
    float* __restrict__ Cf, long long sCf,
    __nv_bfloat16* __restrict__ Ch, __nv_bfloat16* __restrict__ Cl, long long sC,
    __nv_bfloat16* __restrict__ Vh, long long sV,
    const float* __restrict__ Res, long long sRes)
{
    extern __shared__ char smem[];
    const uint32_t sb = smem_u32(smem);
    const int tid = threadIdx.x, lid = tid & 31, wid = tid >> 5;
    const int bz = blockIdx.z;
    const int m0 = blockIdx.y * 128, n0 = blockIdx.x * 128;

    Ah += (long long)bz * sA;  Al += (long long)bz * sA;
    Bh += (long long)bz * sB;
    if (SB) Bl += (long long)bz * sB;

    const int wm0 = (wid >> 2) * 64, wn0 = (wid & 3) * 32;

    // ---- loader (thread covers seg=tid&7, rows tid>>3 + i*32) ----
    const int l_r0 = tid >> 3, l_seg = tid & 7;
    auto load_stage = [&](int s, int kIter) {
        const uint32_t dst = sb + s * 65536;
        const int k0 = kIter << 6;
        #pragma unroll
        for (int i = 0; i < 4; i++) {
            const int row = l_r0 + i * 32;
            const uint32_t so = row * 128 + ((l_seg ^ (row & 7)) << 4);
            const size_t ga = (size_t)(m0 + row) * lda + k0 + l_seg * 8;
            const size_t gb = (size_t)(n0 + row) * ldb + k0 + l_seg * 8;
            cp16(dst + so,         Ah + ga);
            cp16(dst + 16384 + so, Al + ga);
            cp16(dst + 32768 + so, Bh + gb);
            if (SB) cp16(dst + 49152 + so, Bl + gb);
        }
    };

    // ---- fragment lane constants ----
    const int matq = lid >> 3, mr = lid & 7;
    const int a_rb = ((matq & 1) << 3) + mr;   // row-in-16 for A
    const int a_ks = matq >> 1;                // k-16B-seg select for A
    const int b_rb = (((matq >> 1) & 1) << 3) + mr;
    const int b_ks = matq & 1;

    float acc[4][4][4];
    #pragma unroll
    for (int i = 0; i < 4; i++)
        #pragma unroll
        for (int j = 0; j < 4; j++)
            #pragma unroll
            for (int q = 0; q < 4; q++) acc[i][j][q] = 0.f;

    const int niter = K >> 6;
    load_stage(0, 0); CP_COMMIT();
    load_stage(1, 1); CP_COMMIT();
    CP_WAIT1();
    __syncthreads();

    for (int it = 0; it < niter; it++) {
        const uint32_t Ab = sb + (it & 1) * 65536;
        #pragma unroll
        for (int ks = 0; ks < 4; ks++) {
            uint32_t ah[4][4], al[4][4], bh[2][4], bl[2][4];
            #pragma unroll
            for (int mt = 0; mt < 4; mt++) {
                const int r = wm0 + mt * 16 + a_rb;
                const uint32_t ad = Ab + r * 128 + (((ks * 2 + a_ks) ^ (r & 7)) << 4);
                ldm4(ah[mt], ad);
                ldm4(al[mt], ad + 16384);
            }
            #pragma unroll
            for (int g = 0; g < 2; g++) {
                const int r = wn0 + g * 16 + b_rb;
                const uint32_t bd = Ab + 32768 + r * 128 + (((ks * 2 + b_ks) ^ (r & 7)) << 4);
                ldm4(bh[g], bd);
                if (SB) ldm4(bl[g], bd + 16384);
            }
            #pragma unroll
            for (int mt = 0; mt < 4; mt++)
                #pragma unroll
                for (int nt = 0; nt < 4; nt++) {
                    const uint32_t* bhp = &bh[nt >> 1][(nt & 1) * 2];
                    mma16816(acc[mt][nt], ah[mt], bhp);
                    if (SB) {
                        const uint32_t* blp = &bl[nt >> 1][(nt & 1) * 2];
                        mma16816(acc[mt][nt], ah[mt], blp);
                    }
                    mma16816(acc[mt][nt], al[mt], bhp);
                }
        }
        __syncthreads();
        if (it + 2 < niter) {
            load_stage(it & 1, it + 2); CP_COMMIT(); CP_WAIT1();
        } else {
            CP_COMMIT(); CP_WAIT0();
        }
        __syncthreads();
    }

    // ---- stage fp32 tile to smem (stride 133: conflict-free transpose) ----
    float* cs = reinterpret_cast<float*>(smem);
    #pragma unroll
    for (int mt = 0; mt < 4; mt++) {
        const int r = wm0 + mt * 16 + (lid >> 2);
        #pragma unroll
        for (int nt = 0; nt < 4; nt++) {
            const int c = wn0 + nt * 8 + ((lid & 3) << 1);
            cs[r * 133 + c]           = acc[mt][nt][0];
            cs[r * 133 + c + 1]       = acc[mt][nt][1];
            cs[(r + 8) * 133 + c]     = acc[mt][nt][2];
            cs[(r + 8) * 133 + c + 1] = acc[mt][nt][3];
        }
    }
    __syncthreads();

    // ---- epilogue ----
    if (EPI == 0) {
        if (n0 < 1024) {   // q/k rows: [tok][1024] split bf16, +bias
            const float4 bv = *reinterpret_cast<const float4*>(&bias[n0 + lid * 4]);
            __nv_bfloat16* H = Ch + (size_t)bz * sC;
            __nv_bfloat16* L = Cl + (size_t)bz * sC;
            for (int r = wid; r < 128; r += 8) {
                const float* row = cs + r * 133 + lid * 4;
                const float v0 = row[0] + bv.x, v1 = row[1] + bv.y;
                const float v2 = row[2] + bv.z, v3 = row[3] + bv.w;
                const size_t o = (size_t)(m0 + r) * 1024 + n0 + lid * 4;
                uint2 hi; hi.x = bpack(v0, v1); hi.y = bpack(v2, v3);
                uint2 lo; lo.x = bpack(bres(v0), bres(v1)); lo.y = bpack(bres(v2), bres(v3));
                *reinterpret_cast<uint2*>(H + o) = hi;
                *reinterpret_cast<uint2*>(L + o) = lo;
            }
        } else {           // v: [c][tok] bf16 (hi only), +bias
            __nv_bfloat16* H = Vh + (size_t)bz * sV;
            for (int c = wid; c < 128; c += 8) {
                const int n = n0 + c;
                const float bvn = bias[n];
                const float v0 = cs[(lid * 4 + 0) * 133 + c] + bvn;
                const float v1 = cs[(lid * 4 + 1) * 133 + c] + bvn;
                const float v2 = cs[(lid * 4 + 2) * 133 + c] + bvn;
                const float v3 = cs[(lid * 4 + 3) * 133 + c] + bvn;
                const size_t o = (size_t)(n - 1024) * HW + m0 + lid * 4;
                uint2 hi; hi.x = bpack(v0, v1); hi.y = bpack(v2, v3);
                *reinterpret_cast<uint2*>(H + o) = hi;
            }
        }
    } else if (EPI == 1) {  // S: fp32 row-major * alpha
        float* C = Cf + (size_t)bz * sCf;
        for (int r = wid; r < 128; r += 8) {
            const float* row = cs + r * 133 + lid * 4;
            float4 v;
            v.x = row[0] * alpha; v.y = row[1] * alpha;
            v.z = row[2] * alpha; v.w = row[3] * alpha;
            *reinterpret_cast<float4*>(C + (size_t)(m0 + r) * HW + n0 + lid * 4) = v;
        }
    } else if (EPI == 2) {  // O^T: [tok][c] split bf16
        __nv_bfloat16* H = Ch + (size_t)bz * sC;
        __nv_bfloat16* L = Cl + (size_t)bz * sC;
        for (int r = wid; r < 128; r += 8) {
            const float* row = cs + r * 133 + lid * 4;
            const float v0 = row[0], v1 = row[1], v2 = row[2], v3 = row[3];
            const size_t o = (size_t)(m0 + r) * CH + n0 + lid * 4;
            uint2 hi; hi.x = bpack(v0, v1); hi.y = bpack(v2, v3);
            uint2 lo; lo.x = bpack(bres(v0), bres(v1)); lo.y = bpack(bres(v2), bres(v3));
            *reinterpret_cast<uint2*>(H + o) = hi;
            *reinterpret_cast<uint2*>(L + o) = lo;
        }
    } else {                // PROJ: out[c][tok] = tile^T + bias + residual (fp32)
        const float* R = Res + (size_t)bz * sRes;
        float* C = Cf + (size_t)bz * sCf;
        for (int c = wid; c < 128; c += 8) {
            const int n = n0 + c;
            const float bvn = bias[n];
            const size_t o = (size_t)n * HW + m0 + lid * 4;
            const float4 rr = *reinterpret_cast<const float4*>(R + o);
            float4 v;
            v.x = cs[(lid * 4 + 0) * 133 + c] + bvn + rr.x;
            v.y = cs[(lid * 4 + 1) * 133 + c] + bvn + rr.y;
            v.z = cs[(lid * 4 + 2) * 133 + c] + bvn + rr.z;
            v.w = cs[(lid * 4 + 3) * 133 + c] + bvn + rr.w;
            *reinterpret_cast<float4*>(C + o) = v;
        }
    }
}

// ---------------- GroupNorm stats ----------------
__global__ __launch_bounds__(256) void gn_stats_kernel(const float* __restrict__ x)
{
    const int bg = blockIdx.x;
    const size_t base = (size_t)bg * 16 * HW;
    const int n = 16 * HW;
    float s = 0.f, ss = 0.f;
    for (int i = threadIdx.x; i < n; i += 256) {
        float v = x[base + i];
        s += v; ss += v * v;
    }
    #pragma unroll
    for (int o = 16; o > 0; o >>= 1) {
        s  += __shfl_xor_sync(0xffffffffu, s,  o);
        ss += __shfl_xor_sync(0xffffffffu, ss, o);
    }
    __shared__ float sh[16];
    const int w = threadIdx.x >> 5, l = threadIdx.x & 31;
    if (l == 0) { sh[w] = s; sh[8 + w] = ss; }
    __syncthreads();
    if (threadIdx.x == 0) {
        float S = 0.f, SS = 0.f;
        #pragma unroll
        for (int i = 0; i < 8; i++) { S += sh[i]; SS += sh[8 + i]; }
        float mean = S / (float)n;
        float var  = SS / (float)n - mean * mean;
        g_mean[bg] = mean;
        g_rstd[bg] = rsqrtf(var + EPS);
    }
}

// ---------------- normalize + transpose + bf16 split ----------------
__global__ __launch_bounds__(256) void normT_kernel(
    const float* __restrict__ x, const float* __restrict__ gamma,
    const float* __restrict__ beta,
    __nv_bfloat16* __restrict__ th, __nv_bfloat16* __restrict__ tl)
{
    __shared__ float tile[64][65];
    const int b = blockIdx.z, c0 = blockIdx.y * 64, t0 = blockIdx.x * 64;
    const int lane = threadIdx.x & 63, r0 = threadIdx.x >> 6;
    #pragma unroll
    for (int r = r0; r < 64; r += 4) {
        const int c = c0 + r;
        const int gr = b * 32 + (c >> 4);
        float v = x[((size_t)b * CH + c) * HW + t0 + lane];
        tile[r][lane] = (v - g_mean[gr]) * g_rstd[gr] * gamma[c] + beta[c];
    }
    __syncthreads();
    #pragma unroll
    for (int r = r0; r < 64; r += 4) {
        const float v = tile[lane][r];
        const size_t o = ((size_t)b * HW + t0 + r) * CH + c0 + lane;
        __nv_bfloat16 hv = __float2bfloat16(v);
        th[o] = hv;
        tl[o] = __float2bfloat16(v - __bfloat162float(hv));
    }
}

// ---------------- weight fp32 -> hi/lo split ----------------
__global__ void wsplit_kernel(const float* __restrict__ in,
                              __nv_bfloat16* __restrict__ h,
                              __nv_bfloat16* __restrict__ l, int n)
{
    int i = blockIdx.x * 256 + threadIdx.x;
    if (i < n) {
        float v = in[i];
        __nv_bfloat16 hv = __float2bfloat16(v);
        h[i] = hv;
        l[i] = __float2bfloat16(v - __bfloat162float(hv));
    }
}

// ---------------- softmax (fp32 in, bf16 split out) ----------------
__global__ __launch_bounds__(256) void softmax_kernel(
    const float* __restrict__ S, __nv_bfloat16* __restrict__ ph,
    __nv_bfloat16* __restrict__ pl)
{
    const size_t base = (size_t)blockIdx.x * HW;
    const float* p = S + base;

    float v[16];
    float mx = -INFINITY;
    #pragma unroll
    for (int i = 0; i < 16; i++) {
        v[i] = p[threadIdx.x + i * 256];
        mx = fmaxf(mx, v[i]);
    }
    #pragma unroll
    for (int o = 16; o > 0; o >>= 1)
        mx = fmaxf(mx, __shfl_xor_sync(0xffffffffu, mx, o));

    __shared__ float sh[10];
    const int w = threadIdx.x >> 5, l = threadIdx.x & 31;
    if (l == 0) sh[w] = mx;
    __syncthreads();
    if (threadIdx.x == 0) {
        float m = sh[0];
        #pragma unroll
        for (int i = 1; i < 8; i++) m = fmaxf(m, sh[i]);
        sh[8] = m;
    }
    __syncthreads();
    mx = sh[8];

    float sum = 0.f;
    #pragma unroll
    for (int i = 0; i < 16; i++) { v[i] = __expf(v[i] - mx); sum += v[i]; }
    #pragma unroll
    for (int o = 16; o > 0; o >>= 1)
        sum += __shfl_xor_sync(0xffffffffu, sum, o);
    if (l == 0) sh[w] = sum;
    __syncthreads();
    if (threadIdx.x == 0) {
        float s = 0.f;
        #pragma unroll
        for (int i = 0; i < 8; i++) s += sh[i];
        sh[9] = 1.f / s;
    }
    __syncthreads();
    const float inv = sh[9];

    #pragma unroll
    for (int i = 0; i < 16; i++) {
        const float pv = v[i] * inv;
        const size_t o = base + threadIdx.x + i * 256;
        __nv_bfloat16 hv = __float2bfloat16(pv);
        ph[o] = hv;
        pl[o] = __float2bfloat16(pv - __bfloat162float(hv));
    }
}

// ---------------- launch ----------------
extern "C" void kernel_launch(void* const* d_in, const int* in_sizes, int n_in,
                              void* d_out, int out_size)
{
    const float* x      = (const float*)d_in[0];
    const float* gamma  = (const float*)d_in[1];
    const float* beta   = (const float*)d_in[2];
    const float* w_qkv  = (const float*)d_in[3];
    const float* b_qkv  = (const float*)d_in[4];
    const float* w_proj = (const float*)d_in[5];
    const float* b_proj = (const float*)d_in[6];
    float* out = (float*)d_out;

    __nv_bfloat16 *xnT_h, *xnT_l, *wqkv_h, *wqkv_l, *wproj_h, *wproj_l;
    __nv_bfloat16 *qk_h, *qk_l, *v_h, *p_h, *p_l, *oT_h, *oT_l;
    float* S;
    cudaGetSymbolAddress((void**)&xnT_h, g_xnT_h);
    cudaGetSymbolAddress((void**)&xnT_l, g_xnT_l);
    cudaGetSymbolAddress((void**)&wqkv_h, g_wqkv_h);
    cudaGetSymbolAddress((void**)&wqkv_l, g_wqkv_l);
    cudaGetSymbolAddress((void**)&wproj_h, g_wproj_h);
    cudaGetSymbolAddress((void**)&wproj_l, g_wproj_l);
    cudaGetSymbolAddress((void**)&qk_h, g_qk_h);
    cudaGetSymbolAddress((void**)&qk_l, g_qk_l);
    cudaGetSymbolAddress((void**)&v_h, g_v_h);
    cudaGetSymbolAddress((void**)&S, g_S);
    cudaGetSymbolAddress((void**)&p_h, g_p_h);
    cudaGetSymbolAddress((void**)&p_l, g_p_l);
    cudaGetSymbolAddress((void**)&oT_h, g_oT_h);
    cudaGetSymbolAddress((void**)&oT_l, g_oT_l);

    cudaFuncSetAttribute((const void*)mma_gemm_kernel<0, true>,  cudaFuncAttributeMaxDynamicSharedMemorySize, SMEM_BYTES);
    cudaFuncSetAttribute((const void*)mma_gemm_kernel<1, false>, cudaFuncAttributeMaxDynamicSharedMemorySize, SMEM_BYTES);
    cudaFuncSetAttribute((const void*)mma_gemm_kernel<2, false>, cudaFuncAttributeMaxDynamicSharedMemorySize, SMEM_BYTES);
    cudaFuncSetAttribute((const void*)mma_gemm_kernel<3, true>,  cudaFuncAttributeMaxDynamicSharedMemorySize, SMEM_BYTES);

    const long long sTok = (long long)HW * CH;
    const long long sQK  = (long long)HW * 1024;
    const long long sS   = (long long)HW * HW;
    const float scale2 = 1.f / sqrtf((float)CH);

    // 1) weight splits
    wsplit_kernel<<<(3 * CH * CH + 255) / 256, 256>>>(w_qkv, wqkv_h, wqkv_l, 3 * CH * CH);
    wsplit_kernel<<<(CH * CH + 255) / 256, 256>>>(w_proj, wproj_h, wproj_l, CH * CH);

    // 2) GroupNorm stats + normalize/transpose/split
    gn_stats_kernel<<<BATCH * 32, 256>>>(x);
    normT_kernel<<<dim3(HW / 64, CH / 64, BATCH), 256>>>(x, gamma, beta, xnT_h, xnT_l);

    // 3) QKV (3-pass): C[tok][oc] = xnT . w_qkv^T  (M=4096, N=1536, K=512)
    mma_gemm_kernel<0, true><<<dim3(12, 32, BATCH), 256, SMEM_BYTES>>>(
        xnT_h, xnT_l, CH, sTok, wqkv_h, wqkv_l, CH, 0,
        CH, 1.f, b_qkv,
        nullptr, 0, qk_h, qk_l, sQK, v_h, sTok, nullptr, 0);

    // 4) S (2-pass): S[i][j] = q . k^T * scale  (M=N=4096, K=512)
    mma_gemm_kernel<1, false><<<dim3(32, 32, BATCH), 256, SMEM_BYTES>>>(
        qk_h, qk_l, 1024, sQK, qk_h + CH, nullptr, 1024, sQK,
        CH, scale2, nullptr,
        S, sS, nullptr, nullptr, 0, nullptr, 0, nullptr, 0);

    // 5) softmax rows -> p hi/lo
    softmax_kernel<<<BATCH * HW, 256>>>(S, p_h, p_l);

    // 6) O (2-pass): O^T[tok][c] = p . v^T  (M=4096, N=512, K=4096)
    mma_gemm_kernel<2, false><<<dim3(4, 32, BATCH), 256, SMEM_BYTES>>>(
        p_h, p_l, HW, sS, v_h, nullptr, HW, sTok,
        HW, 1.f, nullptr,
        nullptr, 0, oT_h, oT_l, sTok, nullptr, 0, nullptr, 0);

    // 7) PROJ (3-pass): out[c][tok] = oT . w_proj^T + b_proj + x  (M=4096, N=512, K=512)
    mma_gemm_kernel<3, true><<<dim3(4, 32, BATCH), 256, SMEM_BYTES>>>(
        oT_h, oT_l, CH, sTok, wproj_h, wproj_l, CH, 0,
        CH, 1.f, b_proj,
        out, sTok, nullptr, nullptr, 0, nullptr, 0, x, sTok);
}